// round 9
// baseline (speedup 1.0000x reference)
#include <cuda_runtime.h>
#include <cfloat>
#include <math.h>

// VectorQuantizer R9: R2 FFMA2 mainloop, BN=64 tiles, 2 CTAs/SM so loads,
// epilogue and barriers of one CTA hide under the other CTA's FFMA2 stream.
// Numerics byte-identical to R2/R8 for idx and y.
// out: [ y (N*D) | idx as float (N) | loss | perplexity | usage | H ]

#define N_FIXED 65536
#define D 256
#define D4 64
#define KCB 1024
#define BN 64
#define XS_STRIDE4 65   // x smem row stride in float4
#define CS_STRIDE 132   // code smem row stride in floats
// floats: xs 64*260 | cs 2*32*132 | e2s 1024 | idx 64 | wsum 8dbl(16f)
#define SMEM_FLOATS (64 * 260 + 2 * 32 * CS_STRIDE + 1024 + 64 + 16)

__device__ float        g_e2[KCB];
__device__ unsigned int g_counts[KCB];
__device__ double       g_partial[1024];

#define FMA2(d, a, b) \
    asm("fma.rn.f32x2 %0, %1, %2, %0;" : "+l"(d) : "l"(a), "l"(b))

__device__ __forceinline__ unsigned long long bcast2(float v) {
    unsigned long long r;
    asm("mov.b64 %0, {%1, %1};" : "=l"(r) : "f"(v));
    return r;
}

__global__ void vq_init_kernel() {
    int t = threadIdx.x;
    if (t < KCB) g_counts[t] = 0u;
}

__global__ void vq_e2_kernel(const float* __restrict__ cb) {
    int row  = blockIdx.x * 8 + (threadIdx.x >> 5);
    int lane = threadIdx.x & 31;
    float s = 0.0f;
#pragma unroll
    for (int j = 0; j < 8; ++j) {
        float v = cb[row * D + lane + j * 32];
        s = fmaf(v, v, s);
    }
#pragma unroll
    for (int m = 16; m >= 1; m >>= 1)
        s += __shfl_xor_sync(0xffffffffu, s, m);
    if (lane == 0) g_e2[row] = s;
}

// ---------------------------------------------------------------------------
// Fused argmin GEMM + epilogue. 64 rows x 1024 codes per CTA, 256 threads,
// per thread 4 rows x 8 codes (FFMA2 pairs). 2 CTAs/SM.
// ---------------------------------------------------------------------------
__global__ void __launch_bounds__(256, 2)
vq_argmin_fused_kernel(const float* __restrict__ x, const float* __restrict__ cb,
                       float* __restrict__ y_out, float* __restrict__ idxf_out) {
    extern __shared__ float smem[];
    float*  xs    = smem;                          // 64*260
    float*  cs    = smem + 64 * 260;               // 2 * 32*CS_STRIDE
    float*  e2s   = cs + 2 * 32 * CS_STRIDE;       // 1024
    int*    idx_s = (int*)(e2s + 1024);            // 64
    double* wsum  = (double*)(idx_s + 64);         // 8

    const int tid = threadIdx.x;
    const int tx  = tid & 15;
    const int ty  = tid >> 4;
    const int n0  = blockIdx.x * BN;

    for (int i = tid; i < KCB; i += 256) e2s[i] = g_e2[i];

    const float4* __restrict__ x4 = (const float4*)x;
    float4* xs4 = (float4*)xs;
#pragma unroll
    for (int u = 0; u < 16; ++u) {
        int f  = tid + u * 256;        // 0..4095
        int r  = f >> 6;
        int d4 = f & 63;
        float4 v = x4[(size_t)(n0 + r) * D4 + d4];
        xs4[r * XS_STRIDE4 + (d4 ^ ((r >> 3) & 7))] = v;
    }
    __syncthreads();

    // x2 per row (EXACT R2 chain: lane tx sums tx*4+q, butterfly 8..1)
    float x2r[4];
#pragma unroll
    for (int i = 0; i < 4; ++i) {
        int r  = ty * 4 + i;
        int sw = (r >> 3) & 7;
        float s = 0.0f;
#pragma unroll
        for (int q = 0; q < 4; ++q) {
            float4 v = xs4[r * XS_STRIDE4 + ((tx * 4 + q) ^ sw)];
            s = fmaf(v.x, v.x, s);
            s = fmaf(v.y, v.y, s);
            s = fmaf(v.z, v.z, s);
            s = fmaf(v.w, v.w, s);
        }
#pragma unroll
        for (int m = 8; m >= 1; m >>= 1)
            s += __shfl_xor_sync(0xffffffffu, s, m, 16);
        x2r[i] = s;
    }

    float rbd[4];
    int   rbk[4];
#pragma unroll
    for (int i = 0; i < 4; ++i) { rbd[i] = FLT_MAX; rbk[i] = 0; }

    const float4* __restrict__ cb4 = (const float4*)cb;

    // preload chunk 0 (kt=0, dt=0), transposed [dd][k]
    {
        float* dst = cs;
#pragma unroll
        for (int u = 0; u < 4; ++u) {
            int f   = tid + u * 256;   // 0..1023
            int kl  = f >> 3;
            int dl4 = f & 7;
            float4 v = cb4[(size_t)kl * D4 + dl4];
            int ddb = dl4 * 4;
            dst[(ddb + 0) * CS_STRIDE + kl] = v.x;
            dst[(ddb + 1) * CS_STRIDE + kl] = v.y;
            dst[(ddb + 2) * CS_STRIDE + kl] = v.z;
            dst[(ddb + 3) * CS_STRIDE + kl] = v.w;
        }
    }
    __syncthreads();

    unsigned long long simp[4][4];   // 4 rows x 4 code-pairs

#pragma unroll 1
    for (int cc = 0; cc < 64; ++cc) {      // kt = cc>>3, dt = cc&7
        const int kt = cc >> 3;
        const int dt = cc & 7;

        if (dt == 0) {
#pragma unroll
            for (int i = 0; i < 4; ++i)
#pragma unroll
                for (int j = 0; j < 4; ++j) simp[i][j] = 0ull;
        }

        float4 pv[4];
        const bool have_next = (cc < 63);
        if (have_next) {
            int nkt = (cc + 1) >> 3, ndt = (cc + 1) & 7;
#pragma unroll
            for (int u = 0; u < 4; ++u) {
                int f   = tid + u * 256;
                int kl  = f >> 3;
                int dl4 = f & 7;
                pv[u] = cb4[(size_t)(nkt * 128 + kl) * D4 + ndt * 8 + dl4];
            }
        }

        const ulonglong2* csb2 =
            (const ulonglong2*)(cs + (cc & 1) * (32 * CS_STRIDE));
#pragma unroll
        for (int dd4 = 0; dd4 < 8; ++dd4) {
            float4 xv[4];
#pragma unroll
            for (int i = 0; i < 4; ++i) {
                int r = ty * 4 + i;
                xv[i] = xs4[r * XS_STRIDE4 + ((dt * 8 + dd4) ^ ((r >> 3) & 7))];
            }
#pragma unroll
            for (int t = 0; t < 4; ++t) {
                int dd = dd4 * 4 + t;
                ulonglong2 c01 = csb2[dd * 33 + tx * 2];
                ulonglong2 c23 = csb2[dd * 33 + tx * 2 + 1];
#pragma unroll
                for (int i = 0; i < 4; ++i) {
                    float xv_s = (t == 0) ? xv[i].x : (t == 1) ? xv[i].y
                               : (t == 2) ? xv[i].z : xv[i].w;
                    unsigned long long xp = bcast2(xv_s);
                    FMA2(simp[i][0], xp, c01.x);
                    FMA2(simp[i][1], xp, c01.y);
                    FMA2(simp[i][2], xp, c23.x);
                    FMA2(simp[i][3], xp, c23.y);
                }
            }
        }

        if (have_next) {
            float* dst = cs + ((cc + 1) & 1) * (32 * CS_STRIDE);
#pragma unroll
            for (int u = 0; u < 4; ++u) {
                int f   = tid + u * 256;
                int kl  = f >> 3;
                int ddb = (f & 7) * 4;
                dst[(ddb + 0) * CS_STRIDE + kl] = pv[u].x;
                dst[(ddb + 1) * CS_STRIDE + kl] = pv[u].y;
                dst[(ddb + 2) * CS_STRIDE + kl] = pv[u].z;
                dst[(ddb + 3) * CS_STRIDE + kl] = pv[u].w;
            }
        }

        // per-tile: local running best (k ascending, strict < keeps first)
        if (dt == 7) {
            const int kb = kt * 128 + tx * 8;
            float4 ea = *(const float4*)&e2s[kb];
            float4 eb = *(const float4*)&e2s[kb + 4];
            float e2v[8] = { ea.x, ea.y, ea.z, ea.w, eb.x, eb.y, eb.z, eb.w };
#pragma unroll
            for (int i = 0; i < 4; ++i) {
#pragma unroll
                for (int jp = 0; jp < 4; ++jp) {
                    unsigned long long s = simp[i][jp];
                    float s0 = __uint_as_float((unsigned)s);
                    float s1 = __uint_as_float((unsigned)(s >> 32));
                    int k0 = kb + jp * 2;
                    float t1 = __fadd_rn(x2r[i], e2v[jp * 2]);
                    float d0 = __fadd_rn(t1, -__fmul_rn(2.0f, s0));
                    if (d0 < rbd[i]) { rbd[i] = d0; rbk[i] = k0; }
                    float t2 = __fadd_rn(x2r[i], e2v[jp * 2 + 1]);
                    float d1 = __fadd_rn(t2, -__fmul_rn(2.0f, s1));
                    if (d1 < rbd[i]) { rbd[i] = d1; rbk[i] = k0 + 1; }
                }
            }
        }
        __syncthreads();
    }

    // final cross-lane reduction (16-lane groups), idx -> smem
#pragma unroll
    for (int i = 0; i < 4; ++i) {
        float bd = rbd[i];
        int   bk = rbk[i];
#pragma unroll
        for (int m = 1; m < 16; m <<= 1) {
            float od = __shfl_xor_sync(0xffffffffu, bd, m, 16);
            int   ok = __shfl_xor_sync(0xffffffffu, bk, m, 16);
            if (od < bd || (od == bd && ok < bk)) { bd = od; bk = ok; }
        }
        if (tx == 0) idx_s[ty * 4 + i] = bk;
    }
    __syncthreads();

    // histogram + idx output
    if (tid < BN) {
        int k = idx_s[tid];
        atomicAdd(&g_counts[k], 1u);
        if (idxf_out) idxf_out[n0 + tid] = (float)k;
    }

    // fused gather: y = fl(x + fl(q - x)); x from smem (exact bits)
    float4* y4 = (float4*)y_out;
    double acc = 0.0;
#pragma unroll 4
    for (int u = 0; u < 16; ++u) {
        int f  = tid + u * 256;
        int r  = f >> 6;
        int d4 = f & 63;
        float4 xv = xs4[r * XS_STRIDE4 + (d4 ^ ((r >> 3) & 7))];
        int k = idx_s[r];
        float4 qv = __ldg(&cb4[(size_t)k * D4 + d4]);
        float tx_ = __fadd_rn(qv.x, -xv.x);
        float ty_ = __fadd_rn(qv.y, -xv.y);
        float tz_ = __fadd_rn(qv.z, -xv.z);
        float tw_ = __fadd_rn(qv.w, -xv.w);
        float4 yv;
        yv.x = __fadd_rn(xv.x, tx_);
        yv.y = __fadd_rn(xv.y, ty_);
        yv.z = __fadd_rn(xv.z, tz_);
        yv.w = __fadd_rn(xv.w, tw_);
        y4[(size_t)(n0 + r) * D4 + d4] = yv;
        acc += (double)tx_ * tx_ + (double)ty_ * ty_ +
               (double)tz_ * tz_ + (double)tw_ * tw_;
    }

#pragma unroll
    for (int m = 16; m >= 1; m >>= 1)
        acc += __shfl_xor_sync(0xffffffffu, acc, m);
    if ((tid & 31) == 0) wsum[tid >> 5] = acc;
    __syncthreads();
    if (tid == 0) {
        double s = 0.0;
#pragma unroll
        for (int i = 0; i < 8; ++i) s += wsum[i];
        g_partial[blockIdx.x] = s;
    }
}

__global__ void __launch_bounds__(1024)
vq_finalize_kernel(float* __restrict__ scal_out, int nblocks) {
    __shared__ double redH[1024];
    __shared__ double redU[1024];
    __shared__ double redS[1024];
    int t = threadIdx.x;

    double s = 0.0;
    for (int i = t; i < nblocks; i += 1024) s += g_partial[i];

    float p    = (float)g_counts[t] * (1.0f / 65536.0f);
    float term = p * log2f(p + 1e-10f);

    redH[t] = -(double)term;
    redU[t] = (p > 0.0f) ? 1.0 : 0.0;
    redS[t] = s;
    __syncthreads();
#pragma unroll
    for (int m = 512; m >= 1; m >>= 1) {
        if (t < m) {
            redH[t] += redH[t + m];
            redU[t] += redU[t + m];
            redS[t] += redS[t + m];
        }
        __syncthreads();
    }
    if (t == 0) {
        double mse  = redS[0] / (double)((size_t)N_FIXED * D);
        float  c     = (float)mse;
        float  loss  = __fadd_rn(__fmul_rn(0.25f, c), c);
        float  H     = (float)redH[0];
        float  perp  = expf(__fmul_rn(H, 0.69314718f));
        float  usage = (float)(redU[0] / 1024.0);
        scal_out[0] = loss;
        scal_out[1] = perp;
        scal_out[2] = usage;
        scal_out[3] = H;
    }
}

extern "C" void kernel_launch(void* const* d_in, const int* in_sizes, int n_in,
                              void* d_out, int out_size) {
    (void)n_in;
    const float* x  = (const float*)d_in[0];
    const float* cb = (const float*)d_in[1];
    float* out = (float*)d_out;

    const int    n  = in_sizes[0] / D;      // 65536
    const size_t ND = (size_t)n * D;

    const long long os = (long long)out_size;
    const int with_idx  = os >= (long long)(ND + (size_t)n);
    const int with_scal = os >= (long long)(ND + (size_t)n + 4);

    const size_t smem_bytes = (size_t)SMEM_FLOATS * sizeof(float);
    cudaFuncSetAttribute(vq_argmin_fused_kernel,
                         cudaFuncAttributeMaxDynamicSharedMemorySize,
                         (int)smem_bytes);

    vq_init_kernel<<<1, 1024>>>();
    vq_e2_kernel<<<KCB / 8, 256>>>(cb);
    vq_argmin_fused_kernel<<<n / BN, 256, smem_bytes>>>(
        x, cb, out, with_idx ? (out + ND) : (float*)0);
    if (with_scal)
        vq_finalize_kernel<<<1, 1024>>>(out + ND + n, n / BN);
}

// round 10
// speedup vs baseline: 1.4996x; 1.4996x over previous
#include <cuda_runtime.h>
#include <cfloat>
#include <math.h>

// VectorQuantizer R10: FFMA2 mainloop with the proven 8x8 per-thread tile,
// BN=64 rows via 128 threads -> ~105KB smem -> 2 CTAs/SM (overlap of loads,
// epilogue, barriers) and 1024 tiles (wave quantization 15% -> ~1%).
// Numerics byte-identical to R2/R8 for idx and y.
// out: [ y (N*D) | idx as float (N) | loss | perplexity | usage | H ]

#define N_FIXED 65536
#define D 256
#define D4 64
#define KCB 1024
#define BN 64
#define NT 128          // threads per CTA
#define XS_STRIDE4 65   // x smem row stride in float4
#define CS_STRIDE 132   // code smem row stride in floats
// floats: xs 64*260 | cs 2*32*132 | e2s 1024 | idx 64 | wsum 4 dbl (8f)
#define SMEM_FLOATS (64 * 260 + 2 * 32 * CS_STRIDE + 1024 + 64 + 8)

__device__ float        g_e2[KCB];
__device__ unsigned int g_counts[KCB];
__device__ double       g_partial[1024];

#define FMA2(d, a, b) \
    asm("fma.rn.f32x2 %0, %1, %2, %0;" : "+l"(d) : "l"(a), "l"(b))

__device__ __forceinline__ unsigned long long bcast2(float v) {
    unsigned long long r;
    asm("mov.b64 %0, {%1, %1};" : "=l"(r) : "f"(v));
    return r;
}

__global__ void vq_init_kernel() {
    int t = threadIdx.x;
    if (t < KCB) g_counts[t] = 0u;
}

__global__ void vq_e2_kernel(const float* __restrict__ cb) {
    int row  = blockIdx.x * 8 + (threadIdx.x >> 5);
    int lane = threadIdx.x & 31;
    float s = 0.0f;
#pragma unroll
    for (int j = 0; j < 8; ++j) {
        float v = cb[row * D + lane + j * 32];
        s = fmaf(v, v, s);
    }
#pragma unroll
    for (int m = 16; m >= 1; m >>= 1)
        s += __shfl_xor_sync(0xffffffffu, s, m);
    if (lane == 0) g_e2[row] = s;
}

// ---------------------------------------------------------------------------
// Fused argmin GEMM + epilogue. 64 rows x 1024 codes per CTA, 128 threads
// (tx 16 x ty 8), per thread 8 rows x 8 codes (FFMA2 pairs). 2 CTAs/SM.
// ---------------------------------------------------------------------------
__global__ void __launch_bounds__(NT, 2)
vq_argmin_fused_kernel(const float* __restrict__ x, const float* __restrict__ cb,
                       float* __restrict__ y_out, float* __restrict__ idxf_out) {
    extern __shared__ float smem[];
    float*  xs    = smem;                          // 64*260
    float*  cs    = smem + 64 * 260;               // 2 * 32*CS_STRIDE
    float*  e2s   = cs + 2 * 32 * CS_STRIDE;       // 1024
    int*    idx_s = (int*)(e2s + 1024);            // 64
    double* wsum  = (double*)(idx_s + 64);         // 4

    const int tid = threadIdx.x;
    const int tx  = tid & 15;
    const int ty  = tid >> 4;                      // 0..7
    const int n0  = blockIdx.x * BN;

    for (int i = tid; i < KCB; i += NT) e2s[i] = g_e2[i];

    const float4* __restrict__ x4 = (const float4*)x;
    float4* xs4 = (float4*)xs;
#pragma unroll
    for (int u = 0; u < 32; ++u) {
        int f  = tid + u * NT;         // 0..4095
        int r  = f >> 6;
        int d4 = f & 63;
        float4 v = x4[(size_t)(n0 + r) * D4 + d4];
        xs4[r * XS_STRIDE4 + (d4 ^ ((r >> 3) & 7))] = v;
    }
    __syncthreads();

    // x2 per row (EXACT R2 chain)
    float x2r[8];
#pragma unroll
    for (int i = 0; i < 8; ++i) {
        int r  = ty * 8 + i;
        int sw = (r >> 3) & 7;
        float s = 0.0f;
#pragma unroll
        for (int q = 0; q < 4; ++q) {
            float4 v = xs4[r * XS_STRIDE4 + ((tx * 4 + q) ^ sw)];
            s = fmaf(v.x, v.x, s);
            s = fmaf(v.y, v.y, s);
            s = fmaf(v.z, v.z, s);
            s = fmaf(v.w, v.w, s);
        }
#pragma unroll
        for (int m = 8; m >= 1; m >>= 1)
            s += __shfl_xor_sync(0xffffffffu, s, m, 16);
        x2r[i] = s;
    }

    float rbd[8];
    int   rbk[8];
#pragma unroll
    for (int i = 0; i < 8; ++i) { rbd[i] = FLT_MAX; rbk[i] = 0; }

    const float4* __restrict__ cb4 = (const float4*)cb;

    // preload chunk 0 (kt=0, dt=0), transposed [dd][k]
    {
        float* dst = cs;
#pragma unroll
        for (int u = 0; u < 8; ++u) {
            int f   = tid + u * NT;    // 0..1023
            int kl  = f >> 3;
            int dl4 = f & 7;
            float4 v = cb4[(size_t)kl * D4 + dl4];
            int ddb = dl4 * 4;
            dst[(ddb + 0) * CS_STRIDE + kl] = v.x;
            dst[(ddb + 1) * CS_STRIDE + kl] = v.y;
            dst[(ddb + 2) * CS_STRIDE + kl] = v.z;
            dst[(ddb + 3) * CS_STRIDE + kl] = v.w;
        }
    }
    __syncthreads();

    unsigned long long simp[8][4];

#pragma unroll 1
    for (int cc = 0; cc < 64; ++cc) {      // kt = cc>>3, dt = cc&7
        const int kt = cc >> 3;
        const int dt = cc & 7;

        if (dt == 0) {
#pragma unroll
            for (int i = 0; i < 8; ++i)
#pragma unroll
                for (int j = 0; j < 4; ++j) simp[i][j] = 0ull;
        }

        float4 pv[8];
        const bool have_next = (cc < 63);
        if (have_next) {
            int nkt = (cc + 1) >> 3, ndt = (cc + 1) & 7;
#pragma unroll
            for (int u = 0; u < 8; ++u) {
                int f   = tid + u * NT;
                int kl  = f >> 3;
                int dl4 = f & 7;
                pv[u] = cb4[(size_t)(nkt * 128 + kl) * D4 + ndt * 8 + dl4];
            }
        }

        const ulonglong2* csb2 =
            (const ulonglong2*)(cs + (cc & 1) * (32 * CS_STRIDE));
#pragma unroll
        for (int dd4 = 0; dd4 < 8; ++dd4) {
            float4 xv[8];
#pragma unroll
            for (int i = 0; i < 8; ++i) {
                int r = ty * 8 + i;
                xv[i] = xs4[r * XS_STRIDE4 + ((dt * 8 + dd4) ^ ((r >> 3) & 7))];
            }
#pragma unroll
            for (int t = 0; t < 4; ++t) {
                int dd = dd4 * 4 + t;
                ulonglong2 c01 = csb2[dd * 33 + tx * 2];
                ulonglong2 c23 = csb2[dd * 33 + tx * 2 + 1];
#pragma unroll
                for (int i = 0; i < 8; ++i) {
                    float xv_s = (t == 0) ? xv[i].x : (t == 1) ? xv[i].y
                               : (t == 2) ? xv[i].z : xv[i].w;
                    unsigned long long xp = bcast2(xv_s);
                    FMA2(simp[i][0], xp, c01.x);
                    FMA2(simp[i][1], xp, c01.y);
                    FMA2(simp[i][2], xp, c23.x);
                    FMA2(simp[i][3], xp, c23.y);
                }
            }
        }

        if (have_next) {
            float* dst = cs + ((cc + 1) & 1) * (32 * CS_STRIDE);
#pragma unroll
            for (int u = 0; u < 8; ++u) {
                int f   = tid + u * NT;
                int kl  = f >> 3;
                int ddb = (f & 7) * 4;
                dst[(ddb + 0) * CS_STRIDE + kl] = pv[u].x;
                dst[(ddb + 1) * CS_STRIDE + kl] = pv[u].y;
                dst[(ddb + 2) * CS_STRIDE + kl] = pv[u].z;
                dst[(ddb + 3) * CS_STRIDE + kl] = pv[u].w;
            }
        }

        // per-tile: local running best (k ascending, strict < keeps first)
        if (dt == 7) {
            const int kb = kt * 128 + tx * 8;
            float4 ea = *(const float4*)&e2s[kb];
            float4 eb = *(const float4*)&e2s[kb + 4];
            float e2v[8] = { ea.x, ea.y, ea.z, ea.w, eb.x, eb.y, eb.z, eb.w };
#pragma unroll
            for (int i = 0; i < 8; ++i) {
#pragma unroll
                for (int jp = 0; jp < 4; ++jp) {
                    unsigned long long s = simp[i][jp];
                    float s0 = __uint_as_float((unsigned)s);
                    float s1 = __uint_as_float((unsigned)(s >> 32));
                    int k0 = kb + jp * 2;
                    float t1 = __fadd_rn(x2r[i], e2v[jp * 2]);
                    float d0 = __fadd_rn(t1, -__fmul_rn(2.0f, s0));
                    if (d0 < rbd[i]) { rbd[i] = d0; rbk[i] = k0; }
                    float t2 = __fadd_rn(x2r[i], e2v[jp * 2 + 1]);
                    float d1 = __fadd_rn(t2, -__fmul_rn(2.0f, s1));
                    if (d1 < rbd[i]) { rbd[i] = d1; rbk[i] = k0 + 1; }
                }
            }
        }
        __syncthreads();
    }

    // final cross-lane reduction (16-lane groups), idx -> smem
#pragma unroll
    for (int i = 0; i < 8; ++i) {
        float bd = rbd[i];
        int   bk = rbk[i];
#pragma unroll
        for (int m = 1; m < 16; m <<= 1) {
            float od = __shfl_xor_sync(0xffffffffu, bd, m, 16);
            int   ok = __shfl_xor_sync(0xffffffffu, bk, m, 16);
            if (od < bd || (od == bd && ok < bk)) { bd = od; bk = ok; }
        }
        if (tx == 0) idx_s[ty * 8 + i] = bk;
    }
    __syncthreads();

    // histogram + idx output
    if (tid < BN) {
        int k = idx_s[tid];
        atomicAdd(&g_counts[k], 1u);
        if (idxf_out) idxf_out[n0 + tid] = (float)k;
    }

    // fused gather: y = fl(x + fl(q - x)); x from smem (exact bits)
    float4* y4 = (float4*)y_out;
    double acc = 0.0;
#pragma unroll 4
    for (int u = 0; u < 32; ++u) {
        int f  = tid + u * NT;
        int r  = f >> 6;
        int d4 = f & 63;
        float4 xv = xs4[r * XS_STRIDE4 + (d4 ^ ((r >> 3) & 7))];
        int k = idx_s[r];
        float4 qv = __ldg(&cb4[(size_t)k * D4 + d4]);
        float tx_ = __fadd_rn(qv.x, -xv.x);
        float ty_ = __fadd_rn(qv.y, -xv.y);
        float tz_ = __fadd_rn(qv.z, -xv.z);
        float tw_ = __fadd_rn(qv.w, -xv.w);
        float4 yv;
        yv.x = __fadd_rn(xv.x, tx_);
        yv.y = __fadd_rn(xv.y, ty_);
        yv.z = __fadd_rn(xv.z, tz_);
        yv.w = __fadd_rn(xv.w, tw_);
        y4[(size_t)(n0 + r) * D4 + d4] = yv;
        acc += (double)tx_ * tx_ + (double)ty_ * ty_ +
               (double)tz_ * tz_ + (double)tw_ * tw_;
    }

#pragma unroll
    for (int m = 16; m >= 1; m >>= 1)
        acc += __shfl_xor_sync(0xffffffffu, acc, m);
    if ((tid & 31) == 0) wsum[tid >> 5] = acc;
    __syncthreads();
    if (tid == 0) {
        double s = 0.0;
#pragma unroll
        for (int i = 0; i < 4; ++i) s += wsum[i];
        g_partial[blockIdx.x] = s;
    }
}

__global__ void __launch_bounds__(1024)
vq_finalize_kernel(float* __restrict__ scal_out, int nblocks) {
    __shared__ double redH[1024];
    __shared__ double redU[1024];
    __shared__ double redS[1024];
    int t = threadIdx.x;

    double s = 0.0;
    for (int i = t; i < nblocks; i += 1024) s += g_partial[i];

    float p    = (float)g_counts[t] * (1.0f / 65536.0f);
    float term = p * log2f(p + 1e-10f);

    redH[t] = -(double)term;
    redU[t] = (p > 0.0f) ? 1.0 : 0.0;
    redS[t] = s;
    __syncthreads();
#pragma unroll
    for (int m = 512; m >= 1; m >>= 1) {
        if (t < m) {
            redH[t] += redH[t + m];
            redU[t] += redU[t + m];
            redS[t] += redS[t + m];
        }
        __syncthreads();
    }
    if (t == 0) {
        double mse  = redS[0] / (double)((size_t)N_FIXED * D);
        float  c     = (float)mse;
        float  loss  = __fadd_rn(__fmul_rn(0.25f, c), c);
        float  H     = (float)redH[0];
        float  perp  = expf(__fmul_rn(H, 0.69314718f));
        float  usage = (float)(redU[0] / 1024.0);
        scal_out[0] = loss;
        scal_out[1] = perp;
        scal_out[2] = usage;
        scal_out[3] = H;
    }
}

extern "C" void kernel_launch(void* const* d_in, const int* in_sizes, int n_in,
                              void* d_out, int out_size) {
    (void)n_in;
    const float* x  = (const float*)d_in[0];
    const float* cb = (const float*)d_in[1];
    float* out = (float*)d_out;

    const int    n  = in_sizes[0] / D;      // 65536
    const size_t ND = (size_t)n * D;

    const long long os = (long long)out_size;
    const int with_idx  = os >= (long long)(ND + (size_t)n);
    const int with_scal = os >= (long long)(ND + (size_t)n + 4);

    const size_t smem_bytes = (size_t)SMEM_FLOATS * sizeof(float);
    cudaFuncSetAttribute(vq_argmin_fused_kernel,
                         cudaFuncAttributeMaxDynamicSharedMemorySize,
                         (int)smem_bytes);

    vq_init_kernel<<<1, 1024>>>();
    vq_e2_kernel<<<KCB / 8, 256>>>(cb);
    vq_argmin_fused_kernel<<<n / BN, NT, smem_bytes>>>(
        x, cb, out, with_idx ? (out + ND) : (float*)0);
    if (with_scal)
        vq_finalize_kernel<<<1, 1024>>>(out + ND + n, n / BN);
}